// round 1
// baseline (speedup 1.0000x reference)
#include <cuda_runtime.h>
#include <cstdint>

// Problem constants (fixed by the reference).
#define D_MODEL   1024
#define NUM_HEADS 16
#define HEAD_DIM  64
#define SEQ       2048
#define BATCH     2
#define MTOT      (BATCH * SEQ)   // 4096 token rows

// ---------------------------------------------------------------------------
// Scratch (allocation-free rule: device globals). 4 x 16 MB fp32.
// g_q/g_k/g_v hold projections in [B,H,S,hd]; g_ao holds attention out [B*S, D].
// ---------------------------------------------------------------------------
__device__ float g_q [BATCH * NUM_HEADS * SEQ * HEAD_DIM];
__device__ float g_k [BATCH * NUM_HEADS * SEQ * HEAD_DIM];
__device__ float g_v [BATCH * NUM_HEADS * SEQ * HEAD_DIM];
__device__ float g_ao[MTOT * D_MODEL];

// ---------------------------------------------------------------------------
// Small PTX helpers
// ---------------------------------------------------------------------------
__device__ __forceinline__ unsigned tf32u(float f) {
    unsigned u;
    asm("cvt.rna.tf32.f32 %0, %1;" : "=r"(u) : "f"(f));
    return u;
}

// D = A(16x8, row) * B(8x8, col) + D, tf32 in / f32 accum
__device__ __forceinline__ void mma8(float c[4], const unsigned a[4],
                                     unsigned b0, unsigned b1) {
    asm volatile(
        "mma.sync.aligned.m16n8k8.row.col.f32.tf32.tf32.f32 "
        "{%0,%1,%2,%3},{%4,%5,%6,%7},{%8,%9},{%0,%1,%2,%3};"
        : "+f"(c[0]), "+f"(c[1]), "+f"(c[2]), "+f"(c[3])
        : "r"(a[0]), "r"(a[1]), "r"(a[2]), "r"(a[3]), "r"(b0), "r"(b1));
}

__device__ __forceinline__ void cp16(void* sdst, const void* gsrc) {
    unsigned s = (unsigned)__cvta_generic_to_shared(sdst);
    asm volatile("cp.async.cg.shared.global [%0], [%1], 16;\n"
                 :: "r"(s), "l"(gsrc));
}

// ---------------------------------------------------------------------------
// NT GEMM: C[m,n] = sum_k A[m,k] * W[n,k] + bias[n]
//   A: [M, K] row-major (M = 4096), W: [N, K] row-major, K = N = 1024.
// Tiles: 128x128x16, 256 threads (8 warps, 2x4), warp tile 64x32.
// MODE 0: C row-major [M, N] (final output)
// MODE 1: scatter to [B, H, S, hd]  (m = b*S+s, n = h*64+d)
// ---------------------------------------------------------------------------
#define GBK 16
#define SA  20   // smem row stride (floats): 8r*? -> (r*20+c)%32 all-distinct

template <int MODE>
__global__ __launch_bounds__(256)
void gemm_nt(const float* __restrict__ A, const float* __restrict__ W,
             const float* __restrict__ bias, float* __restrict__ C,
             int K, int N)
{
    __shared__ float As[2][128][SA];
    __shared__ float Bs[2][128][SA];

    const int tid  = threadIdx.x;
    const int lane = tid & 31, wid = tid >> 5;
    const int wm = wid & 1, wn = wid >> 1;          // 2 x 4 warp grid
    const int m0 = blockIdx.y * 128, n0 = blockIdx.x * 128;
    const int g = lane >> 2, t = lane & 3;

    float acc[4][4][4];
#pragma unroll
    for (int i = 0; i < 4; i++)
#pragma unroll
        for (int j = 0; j < 4; j++)
#pragma unroll
            for (int e = 0; e < 4; e++) acc[i][j][e] = 0.f;

    // stage issue: 128 rows x 16 cols per matrix = 512 float4; 2 per thread
    auto issue = [&](int s, int k0) {
#pragma unroll
        for (int i = 0; i < 2; i++) {
            int lin = tid + i * 256;
            int r = lin >> 2, c4 = lin & 3;
            cp16(&As[s][r][c4 * 4], A + (size_t)(m0 + r) * K + k0 + c4 * 4);
            cp16(&Bs[s][r][c4 * 4], W + (size_t)(n0 + r) * K + k0 + c4 * 4);
        }
        asm volatile("cp.async.commit_group;\n");
    };

    issue(0, 0);
    const int T = K / GBK;   // 64
    for (int tt = 0; tt < T; tt++) {
        const int s = tt & 1;
        if (tt + 1 < T) {
            issue(s ^ 1, (tt + 1) * GBK);
            asm volatile("cp.async.wait_group 1;\n");
        } else {
            asm volatile("cp.async.wait_group 0;\n");
        }
        __syncthreads();

#pragma unroll
        for (int kk = 0; kk < 2; kk++) {
            unsigned af[4][4], bf[4][2];
#pragma unroll
            for (int mt = 0; mt < 4; mt++) {
                int r = wm * 64 + mt * 16 + g, c = kk * 8 + t;
                af[mt][0] = tf32u(As[s][r    ][c    ]);
                af[mt][1] = tf32u(As[s][r + 8][c    ]);
                af[mt][2] = tf32u(As[s][r    ][c + 4]);
                af[mt][3] = tf32u(As[s][r + 8][c + 4]);
            }
#pragma unroll
            for (int nt = 0; nt < 4; nt++) {
                int rn = wn * 32 + nt * 8 + g, c = kk * 8 + t;
                bf[nt][0] = tf32u(Bs[s][rn][c    ]);
                bf[nt][1] = tf32u(Bs[s][rn][c + 4]);
            }
#pragma unroll
            for (int mt = 0; mt < 4; mt++)
#pragma unroll
                for (int nt = 0; nt < 4; nt++)
                    mma8(acc[mt][nt], af[mt], bf[nt][0], bf[nt][1]);
        }
        __syncthreads();
    }

    // epilogue
#pragma unroll
    for (int mt = 0; mt < 4; mt++) {
#pragma unroll
        for (int nt = 0; nt < 4; nt++) {
            const int row = m0 + wm * 64 + mt * 16 + g;
            const int col = n0 + wn * 32 + nt * 8 + 2 * t;
            const float b0v = bias[col], b1v = bias[col + 1];
#pragma unroll
            for (int half = 0; half < 2; half++) {
                const int r = row + half * 8;
                float2 v;
                v.x = acc[mt][nt][half * 2 + 0] + b0v;
                v.y = acc[mt][nt][half * 2 + 1] + b1v;
                if (MODE == 0) {
                    *reinterpret_cast<float2*>(C + (size_t)r * N + col) = v;
                } else {
                    const int bb = r >> 11, ss = r & (SEQ - 1);
                    const int hh = col >> 6, dd = col & (HEAD_DIM - 1);
                    *reinterpret_cast<float2*>(
                        C + (((size_t)(bb * NUM_HEADS + hh) * SEQ + ss)
                             << 6) + dd) = v;
                }
            }
        }
    }
}

// ---------------------------------------------------------------------------
// Flash attention (causal), one block per (b, h, 64-row q tile).
// 128 threads = 4 warps; warp w owns q rows [w*16, w*16+16).
// smem: QP[64][68] (Q tile, then reused as P tile), Ks[64][68], Vt[64][68]
// (V transposed to [d][k]).  Stride 68 -> (4r + c) mod 32 all distinct for the
// 8-row x 4-col fragment LDS pattern.
// ---------------------------------------------------------------------------
#define SK 68

__global__ __launch_bounds__(128)
void attn_kernel(const float* __restrict__ gq, const float* __restrict__ gk,
                 const float* __restrict__ gv, float* __restrict__ gout)
{
    extern __shared__ float sm[];
    float* QP = sm;                 // [64][SK]  Q tile, later P tile
    float* Ks = sm + 64 * SK;       // [64][SK]  K tile [k][d]
    float* Vt = sm + 2 * 64 * SK;   // [64][SK]  V transposed [d][k]

    const int tid  = threadIdx.x;
    const int lane = tid & 31, warp = tid >> 5;
    const int g = lane >> 2, t = lane & 3;
    const int qt = blockIdx.x, h = blockIdx.y, b = blockIdx.z;

    const size_t base = (size_t)(b * NUM_HEADS + h) * SEQ * HEAD_DIM;
    const float* Q  = gq + base + (size_t)qt * 64 * HEAD_DIM;
    const float* Kp = gk + base;
    const float* Vp = gv + base;

    // Q tile -> smem (coalesced float4)
    for (int i = tid; i < 64 * 16; i += 128) {
        int r = i >> 4, c4 = i & 15;
        float4 v4 = reinterpret_cast<const float4*>(Q + r * HEAD_DIM)[c4];
        *reinterpret_cast<float4*>(&QP[r * SK + c4 * 4]) = v4;
    }
    __syncthreads();

    // Q fragments live in registers for the whole kernel
    unsigned qf[8][4];
    {
        const int r = warp * 16 + g;
#pragma unroll
        for (int kk = 0; kk < 8; kk++) {
            const int c = kk * 8 + t;
            qf[kk][0] = tf32u(QP[ r      * SK + c    ]);
            qf[kk][1] = tf32u(QP[(r + 8) * SK + c    ]);
            qf[kk][2] = tf32u(QP[ r      * SK + c + 4]);
            qf[kk][3] = tf32u(QP[(r + 8) * SK + c + 4]);
        }
    }
    __syncthreads();   // QP may now be reused for P

    float oacc[8][4];
#pragma unroll
    for (int i = 0; i < 8; i++)
#pragma unroll
        for (int e = 0; e < 4; e++) oacc[i][e] = 0.f;

    float mrow0 = -1e30f, mrow1 = -1e30f, lsum0 = 0.f, lsum1 = 0.f;
    const float sl = 0.125f * 1.4426950408889634f;  // SCALE * log2(e)
    const int prow = warp * 16 + g;

    for (int j = 0; j <= qt; j++) {
        __syncthreads();  // previous iteration's Ks/Vt reads complete
        const float* Kj = Kp + (size_t)j * 64 * HEAD_DIM;
        const float* Vj = Vp + (size_t)j * 64 * HEAD_DIM;
        for (int i = tid; i < 64 * 16; i += 128) {
            int r = i >> 4, c4 = i & 15;
            float4 v4 = reinterpret_cast<const float4*>(Kj + r * HEAD_DIM)[c4];
            *reinterpret_cast<float4*>(&Ks[r * SK + c4 * 4]) = v4;
            float4 w4 = reinterpret_cast<const float4*>(Vj + r * HEAD_DIM)[c4];
            Vt[(c4 * 4 + 0) * SK + r] = w4.x;
            Vt[(c4 * 4 + 1) * SK + r] = w4.y;
            Vt[(c4 * 4 + 2) * SK + r] = w4.z;
            Vt[(c4 * 4 + 3) * SK + r] = w4.w;
        }
        __syncthreads();

        // S = Q K^T  (warp tile 16 x 64)
        float sacc[8][4];
#pragma unroll
        for (int i = 0; i < 8; i++)
#pragma unroll
            for (int e = 0; e < 4; e++) sacc[i][e] = 0.f;
#pragma unroll
        for (int kk = 0; kk < 8; kk++) {
            const int c = kk * 8 + t;
#pragma unroll
            for (int nt = 0; nt < 8; nt++) {
                const int rn = nt * 8 + g;
                unsigned b0 = tf32u(Ks[rn * SK + c    ]);
                unsigned b1 = tf32u(Ks[rn * SK + c + 4]);
                mma8(sacc[nt], qf[kk], b0, b1);
            }
        }

        // scale into exp2 domain + causal mask (diagonal tile only)
        if (j == qt) {
#pragma unroll
            for (int nt = 0; nt < 8; nt++)
#pragma unroll
                for (int e = 0; e < 4; e++) {
                    const int kcol = nt * 8 + 2 * t + (e & 1);
                    const int qrow = prow + ((e >> 1) << 3);  // local row
                    sacc[nt][e] = (kcol > qrow) ? -1e30f : sacc[nt][e] * sl;
                }
        } else {
#pragma unroll
            for (int nt = 0; nt < 8; nt++)
#pragma unroll
                for (int e = 0; e < 4; e++) sacc[nt][e] *= sl;
        }

        // online softmax: row max across 4 lanes sharing a row
        float mx0 = -1e30f, mx1 = -1e30f;
#pragma unroll
        for (int nt = 0; nt < 8; nt++) {
            mx0 = fmaxf(mx0, fmaxf(sacc[nt][0], sacc[nt][1]));
            mx1 = fmaxf(mx1, fmaxf(sacc[nt][2], sacc[nt][3]));
        }
        mx0 = fmaxf(mx0, __shfl_xor_sync(0xffffffffu, mx0, 1));
        mx0 = fmaxf(mx0, __shfl_xor_sync(0xffffffffu, mx0, 2));
        mx1 = fmaxf(mx1, __shfl_xor_sync(0xffffffffu, mx1, 1));
        mx1 = fmaxf(mx1, __shfl_xor_sync(0xffffffffu, mx1, 2));
        const float nm0 = fmaxf(mrow0, mx0), nm1 = fmaxf(mrow1, mx1);
        const float al0 = exp2f(mrow0 - nm0), al1 = exp2f(mrow1 - nm1);
        mrow0 = nm0; mrow1 = nm1;

        float ps0 = 0.f, ps1 = 0.f;
#pragma unroll
        for (int nt = 0; nt < 8; nt++) {
            const float p0 = exp2f(sacc[nt][0] - nm0);
            const float p1 = exp2f(sacc[nt][1] - nm0);
            const float p2 = exp2f(sacc[nt][2] - nm1);
            const float p3 = exp2f(sacc[nt][3] - nm1);
            ps0 += p0 + p1; ps1 += p2 + p3;
            *reinterpret_cast<float2*>(&QP[ prow      * SK + nt * 8 + 2 * t]) =
                make_float2(p0, p1);
            *reinterpret_cast<float2*>(&QP[(prow + 8) * SK + nt * 8 + 2 * t]) =
                make_float2(p2, p3);
        }
        ps0 += __shfl_xor_sync(0xffffffffu, ps0, 1);
        ps0 += __shfl_xor_sync(0xffffffffu, ps0, 2);
        ps1 += __shfl_xor_sync(0xffffffffu, ps1, 1);
        ps1 += __shfl_xor_sync(0xffffffffu, ps1, 2);
        lsum0 = lsum0 * al0 + ps0;
        lsum1 = lsum1 * al1 + ps1;
#pragma unroll
        for (int nt = 0; nt < 8; nt++) {
            oacc[nt][0] *= al0; oacc[nt][1] *= al0;
            oacc[nt][2] *= al1; oacc[nt][3] *= al1;
        }
        __syncwarp();   // P stores visible to this warp's fragment loads

        // O += P V   (A = P from smem, B = Vt[d][k])
#pragma unroll
        for (int kk = 0; kk < 8; kk++) {
            const int c = kk * 8 + t;
            unsigned pa[4];
            pa[0] = tf32u(QP[ prow      * SK + c    ]);
            pa[1] = tf32u(QP[(prow + 8) * SK + c    ]);
            pa[2] = tf32u(QP[ prow      * SK + c + 4]);
            pa[3] = tf32u(QP[(prow + 8) * SK + c + 4]);
#pragma unroll
            for (int nt = 0; nt < 8; nt++) {
                const int rd = nt * 8 + g;
                unsigned b0 = tf32u(Vt[rd * SK + c    ]);
                unsigned b1 = tf32u(Vt[rd * SK + c + 4]);
                mma8(oacc[nt], pa, b0, b1);
            }
        }
    }

    // epilogue: normalize, scatter to [B*S, D] (attn output rows)
    const float il0 = 1.f / lsum0, il1 = 1.f / lsum1;
    const int qrow = qt * 64 + warp * 16 + g;
    float* O0 = gout + (size_t)(b * SEQ + qrow) * D_MODEL + h * HEAD_DIM;
    float* O1 = O0 + 8 * D_MODEL;
#pragma unroll
    for (int nt = 0; nt < 8; nt++) {
        const int col = nt * 8 + 2 * t;
        *reinterpret_cast<float2*>(O0 + col) =
            make_float2(oacc[nt][0] * il0, oacc[nt][1] * il0);
        *reinterpret_cast<float2*>(O1 + col) =
            make_float2(oacc[nt][2] * il1, oacc[nt][3] * il1);
    }
}

// ---------------------------------------------------------------------------
// Launch
// ---------------------------------------------------------------------------
extern "C" void kernel_launch(void* const* d_in, const int* in_sizes, int n_in,
                              void* d_out, int out_size)
{
    const float* x  = (const float*)d_in[0];
    const float* Wq = (const float*)d_in[1];
    const float* bq = (const float*)d_in[2];
    const float* Wk = (const float*)d_in[3];
    const float* bk = (const float*)d_in[4];
    const float* Wv = (const float*)d_in[5];
    const float* bv = (const float*)d_in[6];
    const float* Wo = (const float*)d_in[7];
    const float* bo = (const float*)d_in[8];
    float* out = (float*)d_out;

    float *q, *k, *v, *ao;
    cudaGetSymbolAddress((void**)&q,  g_q);
    cudaGetSymbolAddress((void**)&k,  g_k);
    cudaGetSymbolAddress((void**)&v,  g_v);
    cudaGetSymbolAddress((void**)&ao, g_ao);

    const dim3 ggrid(D_MODEL / 128, MTOT / 128);   // (8, 32)
    gemm_nt<1><<<ggrid, 256>>>(x, Wq, bq, q, D_MODEL, D_MODEL);
    gemm_nt<1><<<ggrid, 256>>>(x, Wk, bk, k, D_MODEL, D_MODEL);
    gemm_nt<1><<<ggrid, 256>>>(x, Wv, bv, v, D_MODEL, D_MODEL);

    const int smem_bytes = 64 * SK * 3 * (int)sizeof(float);  // 52224
    cudaFuncSetAttribute(attn_kernel,
                         cudaFuncAttributeMaxDynamicSharedMemorySize,
                         smem_bytes);
    const dim3 agrid(SEQ / 64, NUM_HEADS, BATCH);  // (32, 16, 2)
    attn_kernel<<<agrid, 128, smem_bytes>>>(q, k, v, ao);

    gemm_nt<0><<<ggrid, 256>>>(ao, Wo, bo, out, D_MODEL, D_MODEL);
}

// round 3
// speedup vs baseline: 1.2150x; 1.2150x over previous
#include <cuda_runtime.h>
#include <cstdint>

#define D_MODEL   1024
#define NUM_HEADS 16
#define HEAD_DIM  64
#define SEQ       2048
#define BATCH     2
#define MTOT      (BATCH * SEQ)

// ---------------------------------------------------------------------------
// Scratch (device globals; no allocation allowed)
// ---------------------------------------------------------------------------
__device__ float g_q [BATCH * NUM_HEADS * SEQ * HEAD_DIM];
__device__ float g_k [BATCH * NUM_HEADS * SEQ * HEAD_DIM];
__device__ float g_v [BATCH * NUM_HEADS * SEQ * HEAD_DIM];
__device__ float g_ao[MTOT * D_MODEL];
__device__ float g_xr[MTOT * D_MODEL];
__device__ float g_wq[D_MODEL * D_MODEL];
__device__ float g_wk[D_MODEL * D_MODEL];
__device__ float g_wv[D_MODEL * D_MODEL];
__device__ float g_wo[D_MODEL * D_MODEL];

// ---------------------------------------------------------------------------
// Helpers
// ---------------------------------------------------------------------------
__device__ __forceinline__ unsigned tf32u(float f) {
    unsigned u;
    asm("cvt.rna.tf32.f32 %0, %1;" : "=r"(u) : "f"(f));
    return u;
}
__device__ __forceinline__ float tf32f(float f) {
    return __uint_as_float(tf32u(f));
}
__device__ __forceinline__ float ex2f(float x) {
    float y;
    asm("ex2.approx.f32 %0, %1;" : "=f"(y) : "f"(x));
    return y;
}

// D = A(16x8,row) * B(8x8,col)^T + D, tf32 in / f32 accum
__device__ __forceinline__ void mma8(float c[4], const unsigned a[4],
                                     unsigned b0, unsigned b1) {
    asm volatile(
        "mma.sync.aligned.m16n8k8.row.col.f32.tf32.tf32.f32 "
        "{%0,%1,%2,%3},{%4,%5,%6,%7},{%8,%9},{%0,%1,%2,%3};"
        : "+f"(c[0]), "+f"(c[1]), "+f"(c[2]), "+f"(c[3])
        : "r"(a[0]), "r"(a[1]), "r"(a[2]), "r"(a[3]), "r"(b0), "r"(b1));
}

__device__ __forceinline__ void cp16(void* sdst, const void* gsrc) {
    unsigned s = (unsigned)__cvta_generic_to_shared(sdst);
    asm volatile("cp.async.cg.shared.global [%0], [%1], 16;\n"
                 :: "r"(s), "l"(gsrc));
}

// ---------------------------------------------------------------------------
// tf32 pre-round (RNA): inputs become exact tf32 values so inner loops can
// reinterpret bits with no cvt.
// ---------------------------------------------------------------------------
__global__ void round_tf32(const float4* __restrict__ in,
                           float4* __restrict__ out, int n4)
{
    for (int i = blockIdx.x * blockDim.x + threadIdx.x; i < n4;
         i += gridDim.x * blockDim.x) {
        float4 v = in[i];
        v.x = tf32f(v.x); v.y = tf32f(v.y);
        v.z = tf32f(v.z); v.w = tf32f(v.w);
        out[i] = v;
    }
}

// ---------------------------------------------------------------------------
// NT GEMM: C[m,n] = sum_k A[m,k]*W[n,k] + bias[n].  A,W pre-rounded tf32.
// CTA tile 128x128, 128 threads = 4 warps (2x2), warp tile 64x64.
// K-chunk 32, 2-stage cp.async.  1 LDS per mma, no cvt.
// MODE 0: row-major out (fp32, unrounded).  MODE 1: scatter [B,H,S,hd], tf32-rounded.
// ---------------------------------------------------------------------------
#define GSA     36                    // smem row stride (floats): bank = 4g+t
#define GSTAGE  (128 * GSA)           // floats per matrix per stage
#define GSTAGEB (2 * GSTAGE)          // floats per stage (A+B)
#define GSMEM_BYTES (2 * GSTAGEB * 4) // 73728

template <int MODE>
__global__ __launch_bounds__(128)
void gemm_tc(const float* __restrict__ A, const float* __restrict__ W,
             const float* __restrict__ bias, float* __restrict__ C)
{
    extern __shared__ float sm[];
    const int tid = threadIdx.x, lane = tid & 31, wid = tid >> 5;
    const int wm = wid & 1, wn = wid >> 1;          // 2x2 warp grid
    const int m0 = blockIdx.y * 128, n0 = blockIdx.x * 128;
    const int g = lane >> 2, t = lane & 3;

    float acc[4][8][4];
#pragma unroll
    for (int i = 0; i < 4; i++)
#pragma unroll
        for (int j = 0; j < 8; j++)
#pragma unroll
            for (int e = 0; e < 4; e++) acc[i][j][e] = 0.f;

    auto issue = [&](int s, int k0) {
        float* dA = sm + s * GSTAGEB;
        float* dB = dA + GSTAGE;
        const float* Ap = A + (size_t)m0 * D_MODEL + k0;
        const float* Bp = W + (size_t)n0 * D_MODEL + k0;
#pragma unroll
        for (int i = 0; i < 8; i++) {
            const int lin = tid + i * 128;
            const int r = lin >> 3, c4 = lin & 7;
            cp16(dA + r * GSA + c4 * 4, Ap + (size_t)r * D_MODEL + c4 * 4);
            cp16(dB + r * GSA + c4 * 4, Bp + (size_t)r * D_MODEL + c4 * 4);
        }
        asm volatile("cp.async.commit_group;\n" ::: "memory");
    };

    issue(0, 0);
    const int T = D_MODEL / 32;   // 32 chunks
    for (int tt = 0; tt < T; tt++) {
        const int s = tt & 1;
        if (tt + 1 < T) {
            issue(s ^ 1, (tt + 1) * 32);
            asm volatile("cp.async.wait_group 1;\n" ::: "memory");
        } else {
            asm volatile("cp.async.wait_group 0;\n" ::: "memory");
        }
        __syncthreads();

        const unsigned* As = reinterpret_cast<const unsigned*>(sm + s * GSTAGEB);
        const unsigned* Bs = As + GSTAGE;
#pragma unroll
        for (int kk = 0; kk < 4; kk++) {
            const int c = kk * 8 + t;
            unsigned af[4][4], bf[8][2];
#pragma unroll
            for (int mt = 0; mt < 4; mt++) {
                const int r = wm * 64 + mt * 16 + g;
                af[mt][0] = As[ r      * GSA + c    ];
                af[mt][1] = As[(r + 8) * GSA + c    ];
                af[mt][2] = As[ r      * GSA + c + 4];
                af[mt][3] = As[(r + 8) * GSA + c + 4];
            }
#pragma unroll
            for (int nt = 0; nt < 8; nt++) {
                const int rn = wn * 64 + nt * 8 + g;
                bf[nt][0] = Bs[rn * GSA + c    ];
                bf[nt][1] = Bs[rn * GSA + c + 4];
            }
#pragma unroll
            for (int mt = 0; mt < 4; mt++)
#pragma unroll
                for (int nt = 0; nt < 8; nt++)
                    mma8(acc[mt][nt], af[mt], bf[nt][0], bf[nt][1]);
        }
        __syncthreads();
    }

    // epilogue
#pragma unroll
    for (int mt = 0; mt < 4; mt++) {
#pragma unroll
        for (int nt = 0; nt < 8; nt++) {
            const int row = m0 + wm * 64 + mt * 16 + g;
            const int col = n0 + wn * 64 + nt * 8 + 2 * t;
            const float b0v = bias[col], b1v = bias[col + 1];
#pragma unroll
            for (int half = 0; half < 2; half++) {
                const int r = row + half * 8;
                float2 v;
                v.x = acc[mt][nt][half * 2 + 0] + b0v;
                v.y = acc[mt][nt][half * 2 + 1] + b1v;
                if (MODE == 0) {
                    *reinterpret_cast<float2*>(C + (size_t)r * D_MODEL + col) = v;
                } else {
                    v.x = tf32f(v.x); v.y = tf32f(v.y);
                    const int bb = r >> 11, ss = r & (SEQ - 1);
                    const int hh = col >> 6, dd = col & (HEAD_DIM - 1);
                    *reinterpret_cast<float2*>(
                        C + (((size_t)(bb * NUM_HEADS + hh) * SEQ + ss) << 6)
                          + dd) = v;
                }
            }
        }
    }
}

// ---------------------------------------------------------------------------
// Flash attention (causal).  Block = (b, h, 128-row q tile), 4 warps.
// Warp w covers q rows [w*32, w*32+32) => 2 m-frags.  K/V tiles of 64 rows.
// smem: Qs[128][68], Ps[128][68], Ks[64][68], Vt[64][68]  (tf32 bit patterns)
// 1.5 LDS/mma; B-fragments (K / V^T) feed both m-frags.
// ---------------------------------------------------------------------------
#define SKA 68
#define A_SMEM_BYTES ((128 + 128 + 64 + 64) * SKA * 4)   // 104448

__global__ __launch_bounds__(128)
void attn_kernel(const float* __restrict__ gq, const float* __restrict__ gk,
                 const float* __restrict__ gv, float* __restrict__ gout)
{
    extern __shared__ unsigned smu[];
    unsigned* Qs = smu;                    // [128][SKA]
    unsigned* Ps = smu + 128 * SKA;        // [128][SKA]
    unsigned* Ks = smu + 256 * SKA;        // [64][SKA]
    unsigned* Vt = smu + 320 * SKA;        // [64][SKA]  V^T [d][k]

    const int tid  = threadIdx.x;
    const int lane = tid & 31, w = tid >> 5;
    const int g = lane >> 2, t = lane & 3;
    const int qt = gridDim.x - 1 - blockIdx.x;   // long blocks first
    const int h = blockIdx.y, b = blockIdx.z;

    const size_t base = (size_t)(b * NUM_HEADS + h) * SEQ * HEAD_DIM;
    const float* Q  = gq + base + (size_t)qt * 128 * HEAD_DIM;
    const float* Kp = gk + base;
    const float* Vp = gv + base;

    // Q tile -> smem (values already tf32-exact; store bits)
    for (int i = tid; i < 128 * 16; i += 128) {
        const int r = i >> 4, c4 = i & 15;
        float4 v4 = reinterpret_cast<const float4*>(Q + r * HEAD_DIM)[c4];
        *reinterpret_cast<uint4*>(&Qs[r * SKA + c4 * 4]) =
            make_uint4(__float_as_uint(v4.x), __float_as_uint(v4.y),
                       __float_as_uint(v4.z), __float_as_uint(v4.w));
    }

    float oacc[2][8][4];
#pragma unroll
    for (int mt = 0; mt < 2; mt++)
#pragma unroll
        for (int i = 0; i < 8; i++)
#pragma unroll
            for (int e = 0; e < 4; e++) oacc[mt][i][e] = 0.f;

    float mr[4], ls[4];
#pragma unroll
    for (int i = 0; i < 4; i++) { mr[i] = -1e30f; ls[i] = 0.f; }

    const float sl = 0.125f * 1.4426950408889634f;   // SCALE * log2(e)
    const int njt = 2 * qt + 2;                      // 64-row k-tiles

    for (int j = 0; j < njt; j++) {
        __syncthreads();   // prior Ks/Vt reads done
        const float* Kj = Kp + (size_t)j * 64 * HEAD_DIM;
        const float* Vj = Vp + (size_t)j * 64 * HEAD_DIM;
        for (int i = tid; i < 64 * 16; i += 128) {
            const int r = i >> 4, c4 = i & 15;
            float4 v4 = reinterpret_cast<const float4*>(Kj + r * HEAD_DIM)[c4];
            *reinterpret_cast<uint4*>(&Ks[r * SKA + c4 * 4]) =
                make_uint4(__float_as_uint(v4.x), __float_as_uint(v4.y),
                           __float_as_uint(v4.z), __float_as_uint(v4.w));
            float4 w4 = reinterpret_cast<const float4*>(Vj + r * HEAD_DIM)[c4];
            Vt[(c4 * 4 + 0) * SKA + r] = __float_as_uint(w4.x);
            Vt[(c4 * 4 + 1) * SKA + r] = __float_as_uint(w4.y);
            Vt[(c4 * 4 + 2) * SKA + r] = __float_as_uint(w4.z);
            Vt[(c4 * 4 + 3) * SKA + r] = __float_as_uint(w4.w);
        }
        __syncthreads();

        // ---- S = Q K^T  (two 16-row m-frags per warp) ----
        float sacc[2][8][4];
#pragma unroll
        for (int mt = 0; mt < 2; mt++)
#pragma unroll
            for (int i = 0; i < 8; i++)
#pragma unroll
                for (int e = 0; e < 4; e++) sacc[mt][i][e] = 0.f;

#pragma unroll
        for (int kk = 0; kk < 8; kk++) {
            const int c = kk * 8 + t;
            unsigned qa0[4], qa1[4];
            {
                const int r0 = w * 32 + g;
                qa0[0] = Qs[ r0       * SKA + c    ];
                qa0[1] = Qs[(r0 +  8) * SKA + c    ];
                qa0[2] = Qs[ r0       * SKA + c + 4];
                qa0[3] = Qs[(r0 +  8) * SKA + c + 4];
                qa1[0] = Qs[(r0 + 16) * SKA + c    ];
                qa1[1] = Qs[(r0 + 24) * SKA + c    ];
                qa1[2] = Qs[(r0 + 16) * SKA + c + 4];
                qa1[3] = Qs[(r0 + 24) * SKA + c + 4];
            }
#pragma unroll
            for (int nt = 0; nt < 8; nt++) {
                const int rn = nt * 8 + g;
                const unsigned b0 = Ks[rn * SKA + c];
                const unsigned b1 = Ks[rn * SKA + c + 4];
                mma8(sacc[0][nt], qa0, b0, b1);
                mma8(sacc[1][nt], qa1, b0, b1);
            }
        }

        // ---- scale into exp2 domain + causal mask on diagonal tiles ----
        if (j >= 2 * qt) {
#pragma unroll
            for (int mt = 0; mt < 2; mt++)
#pragma unroll
                for (int nt = 0; nt < 8; nt++)
#pragma unroll
                    for (int e = 0; e < 4; e++) {
                        const int colg = j * 64 + nt * 8 + 2 * t + (e & 1);
                        const int rowg = qt * 128 + w * 32 + mt * 16 + g
                                       + ((e >> 1) << 3);
                        sacc[mt][nt][e] = (colg > rowg) ? -1e30f
                                                        : sacc[mt][nt][e] * sl;
                    }
        } else {
#pragma unroll
            for (int mt = 0; mt < 2; mt++)
#pragma unroll
                for (int nt = 0; nt < 8; nt++)
#pragma unroll
                    for (int e = 0; e < 4; e++) sacc[mt][nt][e] *= sl;
        }

        // ---- online softmax (4 row-groups/thread: mt*2 + half) ----
#pragma unroll
        for (int mt = 0; mt < 2; mt++) {
            float mx0 = -1e30f, mx1 = -1e30f;
#pragma unroll
            for (int nt = 0; nt < 8; nt++) {
                mx0 = fmaxf(mx0, fmaxf(sacc[mt][nt][0], sacc[mt][nt][1]));
                mx1 = fmaxf(mx1, fmaxf(sacc[mt][nt][2], sacc[mt][nt][3]));
            }
            mx0 = fmaxf(mx0, __shfl_xor_sync(0xffffffffu, mx0, 1));
            mx0 = fmaxf(mx0, __shfl_xor_sync(0xffffffffu, mx0, 2));
            mx1 = fmaxf(mx1, __shfl_xor_sync(0xffffffffu, mx1, 1));
            mx1 = fmaxf(mx1, __shfl_xor_sync(0xffffffffu, mx1, 2));
            const float nm0 = fmaxf(mr[mt * 2 + 0], mx0);
            const float nm1 = fmaxf(mr[mt * 2 + 1], mx1);
            const float al0 = ex2f(mr[mt * 2 + 0] - nm0);
            const float al1 = ex2f(mr[mt * 2 + 1] - nm1);
            mr[mt * 2 + 0] = nm0; mr[mt * 2 + 1] = nm1;

            const int prow = w * 32 + mt * 16 + g;
            float ps0 = 0.f, ps1 = 0.f;
#pragma unroll
            for (int nt = 0; nt < 8; nt++) {
                const float p0 = ex2f(sacc[mt][nt][0] - nm0);
                const float p1 = ex2f(sacc[mt][nt][1] - nm0);
                const float p2 = ex2f(sacc[mt][nt][2] - nm1);
                const float p3 = ex2f(sacc[mt][nt][3] - nm1);
                ps0 += p0 + p1; ps1 += p2 + p3;
                *reinterpret_cast<uint2*>(&Ps[ prow      * SKA + nt * 8 + 2 * t])
                    = make_uint2(tf32u(p0), tf32u(p1));
                *reinterpret_cast<uint2*>(&Ps[(prow + 8) * SKA + nt * 8 + 2 * t])
                    = make_uint2(tf32u(p2), tf32u(p3));
            }
            ps0 += __shfl_xor_sync(0xffffffffu, ps0, 1);
            ps0 += __shfl_xor_sync(0xffffffffu, ps0, 2);
            ps1 += __shfl_xor_sync(0xffffffffu, ps1, 1);
            ps1 += __shfl_xor_sync(0xffffffffu, ps1, 2);
            ls[mt * 2 + 0] = ls[mt * 2 + 0] * al0 + ps0;
            ls[mt * 2 + 1] = ls[mt * 2 + 1] * al1 + ps1;
#pragma unroll
            for (int nt = 0; nt < 8; nt++) {
                oacc[mt][nt][0] *= al0; oacc[mt][nt][1] *= al0;
                oacc[mt][nt][2] *= al1; oacc[mt][nt][3] *= al1;
            }
        }
        __syncwarp();   // each warp reads only its own P rows

        // ---- O += P V  (A = P, B = V^T) ----
#pragma unroll
        for (int kk = 0; kk < 8; kk++) {
            const int c = kk * 8 + t;
            unsigned pa0[4], pa1[4];
            {
                const int r0 = w * 32 + g;
                pa0[0] = Ps[ r0       * SKA + c    ];
                pa0[1] = Ps[(r0 +  8) * SKA + c    ];
                pa0[2] = Ps[ r0       * SKA + c + 4];
                pa0[3] = Ps[(r0 +  8) * SKA + c + 4];
                pa1[0] = Ps[(r0 + 16) * SKA + c    ];
                pa1[1] = Ps[(r0 + 24) * SKA + c    ];
                pa1[2] = Ps[(r0 + 16) * SKA + c + 4];
                pa1[3] = Ps[(r0 + 24) * SKA + c + 4];
            }
#pragma unroll
            for (int nt = 0; nt < 8; nt++) {
                const int rd = nt * 8 + g;
                const unsigned b0 = Vt[rd * SKA + c];
                const unsigned b1 = Vt[rd * SKA + c + 4];
                mma8(oacc[0][nt], pa0, b0, b1);
                mma8(oacc[1][nt], pa1, b0, b1);
            }
        }
    }

    // ---- epilogue: normalize, tf32-round (feeds final GEMM), scatter ----
#pragma unroll
    for (int mt = 0; mt < 2; mt++) {
        const float il0 = 1.f / ls[mt * 2 + 0];
        const float il1 = 1.f / ls[mt * 2 + 1];
        const int qrow = qt * 128 + w * 32 + mt * 16 + g;
        float* O0 = gout + (size_t)(b * SEQ + qrow) * D_MODEL + h * HEAD_DIM;
        float* O1 = O0 + 8 * D_MODEL;
#pragma unroll
        for (int nt = 0; nt < 8; nt++) {
            const int col = nt * 8 + 2 * t;
            *reinterpret_cast<float2*>(O0 + col) =
                make_float2(tf32f(oacc[mt][nt][0] * il0),
                            tf32f(oacc[mt][nt][1] * il0));
            *reinterpret_cast<float2*>(O1 + col) =
                make_float2(tf32f(oacc[mt][nt][2] * il1),
                            tf32f(oacc[mt][nt][3] * il1));
        }
    }
}

// ---------------------------------------------------------------------------
// Launch
// ---------------------------------------------------------------------------
extern "C" void kernel_launch(void* const* d_in, const int* in_sizes, int n_in,
                              void* d_out, int out_size)
{
    const float* x  = (const float*)d_in[0];
    const float* Wq = (const float*)d_in[1];
    const float* bq = (const float*)d_in[2];
    const float* Wk = (const float*)d_in[3];
    const float* bk = (const float*)d_in[4];
    const float* Wv = (const float*)d_in[5];
    const float* bv = (const float*)d_in[6];
    const float* Wo = (const float*)d_in[7];
    const float* bo = (const float*)d_in[8];
    float* out = (float*)d_out;

    float *q, *k, *v, *ao, *xr, *wq, *wk, *wv, *wo;
    cudaGetSymbolAddress((void**)&q,  g_q);
    cudaGetSymbolAddress((void**)&k,  g_k);
    cudaGetSymbolAddress((void**)&v,  g_v);
    cudaGetSymbolAddress((void**)&ao, g_ao);
    cudaGetSymbolAddress((void**)&xr, g_xr);
    cudaGetSymbolAddress((void**)&wq, g_wq);
    cudaGetSymbolAddress((void**)&wk, g_wk);
    cudaGetSymbolAddress((void**)&wv, g_wv);
    cudaGetSymbolAddress((void**)&wo, g_wo);

    round_tf32<<<1024, 256>>>((const float4*)x,  (float4*)xr, MTOT * D_MODEL / 4);
    round_tf32<<<512,  256>>>((const float4*)Wq, (float4*)wq, D_MODEL * D_MODEL / 4);
    round_tf32<<<512,  256>>>((const float4*)Wk, (float4*)wk, D_MODEL * D_MODEL / 4);
    round_tf32<<<512,  256>>>((const float4*)Wv, (float4*)wv, D_MODEL * D_MODEL / 4);
    round_tf32<<<512,  256>>>((const float4*)Wo, (float4*)wo, D_MODEL * D_MODEL / 4);

    cudaFuncSetAttribute(gemm_tc<0>,
        cudaFuncAttributeMaxDynamicSharedMemorySize, GSMEM_BYTES);
    cudaFuncSetAttribute(gemm_tc<1>,
        cudaFuncAttributeMaxDynamicSharedMemorySize, GSMEM_BYTES);
    cudaFuncSetAttribute(attn_kernel,
        cudaFuncAttributeMaxDynamicSharedMemorySize, A_SMEM_BYTES);

    const dim3 ggrid(D_MODEL / 128, MTOT / 128);   // (8, 32)
    gemm_tc<1><<<ggrid, 128, GSMEM_BYTES>>>(xr, wq, bq, q);
    gemm_tc<1><<<ggrid, 128, GSMEM_BYTES>>>(xr, wk, bk, k);
    gemm_tc<1><<<ggrid, 128, GSMEM_BYTES>>>(xr, wv, bv, v);

    const dim3 agrid(SEQ / 128, NUM_HEADS, BATCH);  // (16, 16, 2)
    attn_kernel<<<agrid, 128, A_SMEM_BYTES>>>(q, k, v, ao);

    gemm_tc<0><<<ggrid, 128, GSMEM_BYTES>>>(ao, wo, bo, out);
}

// round 4
// speedup vs baseline: 1.9837x; 1.6326x over previous
#include <cuda_runtime.h>
#include <cuda_fp16.h>
#include <cstdint>

#define D_MODEL   1024
#define NUM_HEADS 16
#define HEAD_DIM  64
#define SEQ       2048
#define BATCH     2
#define MTOT      (BATCH * SEQ)

// ---------------------------------------------------------------------------
// Scratch (device globals; allocation is forbidden)
// ---------------------------------------------------------------------------
__device__ __half g_q [BATCH * NUM_HEADS * SEQ * HEAD_DIM];
__device__ __half g_k [BATCH * NUM_HEADS * SEQ * HEAD_DIM];
__device__ __half g_v [BATCH * NUM_HEADS * SEQ * HEAD_DIM];
__device__ __half g_ao[MTOT * D_MODEL];
__device__ __half g_xh[MTOT * D_MODEL];
__device__ __half g_wq[D_MODEL * D_MODEL];
__device__ __half g_wk[D_MODEL * D_MODEL];
__device__ __half g_wv[D_MODEL * D_MODEL];
__device__ __half g_wo[D_MODEL * D_MODEL];

// ---------------------------------------------------------------------------
// Helpers
// ---------------------------------------------------------------------------
__device__ __forceinline__ float ex2f(float x) {
    float y;
    asm("ex2.approx.f32 %0, %1;" : "=f"(y) : "f"(x));
    return y;
}

// D(16x8,f32) += A(16x16,f16) * B(16x8,f16 col)  — fp16 k16 mma
__device__ __forceinline__ void mma16(float c[4], const unsigned a[4],
                                      unsigned b0, unsigned b1) {
    asm volatile(
        "mma.sync.aligned.m16n8k16.row.col.f32.f16.f16.f32 "
        "{%0,%1,%2,%3},{%4,%5,%6,%7},{%8,%9},{%0,%1,%2,%3};"
        : "+f"(c[0]), "+f"(c[1]), "+f"(c[2]), "+f"(c[3])
        : "r"(a[0]), "r"(a[1]), "r"(a[2]), "r"(a[3]), "r"(b0), "r"(b1));
}

__device__ __forceinline__ void cp16(void* sdst, const void* gsrc) {
    unsigned s = (unsigned)__cvta_generic_to_shared(sdst);
    asm volatile("cp.async.cg.shared.global [%0], [%1], 16;\n"
                 :: "r"(s), "l"(gsrc));
}

// ldmatrix x2 transposed b16 (for V: row-major [k][n] -> col-major fragment)
__device__ __forceinline__ void ldmx2t(unsigned& r0, unsigned& r1,
                                       unsigned saddr) {
    asm volatile(
        "ldmatrix.sync.aligned.m8n8.x2.trans.shared.b16 {%0,%1}, [%2];"
        : "=r"(r0), "=r"(r1) : "r"(saddr));
}

__device__ __forceinline__ unsigned h2u(__half2 h) {
    return *reinterpret_cast<unsigned*>(&h);
}

// ---------------------------------------------------------------------------
// fp32 -> fp16 convert (RNE). Same mantissa width as tf32 -> same error model.
// ---------------------------------------------------------------------------
__global__ void to_half_k(const float4* __restrict__ in,
                          uint2* __restrict__ out, int n4)
{
    for (int i = blockIdx.x * blockDim.x + threadIdx.x; i < n4;
         i += gridDim.x * blockDim.x) {
        float4 v = in[i];
        uint2 o;
        o.x = h2u(__floats2half2_rn(v.x, v.y));
        o.y = h2u(__floats2half2_rn(v.z, v.w));
        out[i] = o;
    }
}

// ---------------------------------------------------------------------------
// NT GEMM (fp16 in / fp32 accum): C[m,n] = sum_k A[m,k]*W[n,k] + bias[n]
// CTA tile 128x128, 4 warps (2x2), warp tile 64x64. K-chunk 64 (4 k16 steps),
// 2-stage cp.async. smem pair-packed, row stride 36 words (bank = 4g+t).
// MODE 0: fp32 row-major out.  MODE 1: fp16 scatter to [B,H,S,hd].
// ---------------------------------------------------------------------------
#define GSA     36                        // words (half2 pairs) per row
#define GSTAGE  (128 * GSA)               // words per matrix per stage
#define GSMEM_BYTES (2 * 2 * GSTAGE * 4)  // 2 stages x (A+B) = 73728B? no:
// stage holds A+B: 2*GSTAGE words; 2 stages -> 4*GSTAGE words = 73728 B

template <int MODE>
__global__ __launch_bounds__(128)
void gemm_h(const __half* __restrict__ A, const __half* __restrict__ W,
            const float* __restrict__ bias, void* __restrict__ Cv)
{
    extern __shared__ unsigned sm[];
    const int tid = threadIdx.x, lane = tid & 31, wid = tid >> 5;
    const int wm = wid & 1, wn = wid >> 1;
    const int m0 = blockIdx.y * 128, n0 = blockIdx.x * 128;
    const int g = lane >> 2, t = lane & 3;

    float acc[4][8][4];
#pragma unroll
    for (int i = 0; i < 4; i++)
#pragma unroll
        for (int j = 0; j < 8; j++)
#pragma unroll
            for (int e = 0; e < 4; e++) acc[i][j][e] = 0.f;

    auto issue = [&](int s, int k0) {
        unsigned* dA = sm + s * 2 * GSTAGE;
        unsigned* dB = dA + GSTAGE;
        const __half* Ap = A + (size_t)m0 * D_MODEL + k0;
        const __half* Bp = W + (size_t)n0 * D_MODEL + k0;
#pragma unroll
        for (int i = 0; i < 8; i++) {
            const int lin = tid + i * 128;
            const int r = lin >> 3, c8 = lin & 7;   // 8 x 16B per 64-half row
            cp16(dA + r * GSA + c8 * 4, Ap + (size_t)r * D_MODEL + c8 * 8);
            cp16(dB + r * GSA + c8 * 4, Bp + (size_t)r * D_MODEL + c8 * 8);
        }
        asm volatile("cp.async.commit_group;\n" ::: "memory");
    };

    issue(0, 0);
    const int T = D_MODEL / 64;   // 16 chunks
    for (int tt = 0; tt < T; tt++) {
        const int s = tt & 1;
        if (tt + 1 < T) {
            issue(s ^ 1, (tt + 1) * 64);
            asm volatile("cp.async.wait_group 1;\n" ::: "memory");
        } else {
            asm volatile("cp.async.wait_group 0;\n" ::: "memory");
        }
        __syncthreads();

        const unsigned* As = sm + s * 2 * GSTAGE;
        const unsigned* Bs = As + GSTAGE;
#pragma unroll
        for (int kk = 0; kk < 4; kk++) {   // k16 steps
            const int c = kk * 8 + t;
            unsigned af[4][4], bf[8][2];
#pragma unroll
            for (int mt = 0; mt < 4; mt++) {
                const int r = wm * 64 + mt * 16 + g;
                af[mt][0] = As[ r      * GSA + c    ];
                af[mt][1] = As[(r + 8) * GSA + c    ];
                af[mt][2] = As[ r      * GSA + c + 4];
                af[mt][3] = As[(r + 8) * GSA + c + 4];
            }
#pragma unroll
            for (int nt = 0; nt < 8; nt++) {
                const int rn = wn * 64 + nt * 8 + g;
                bf[nt][0] = Bs[rn * GSA + c    ];
                bf[nt][1] = Bs[rn * GSA + c + 4];
            }
#pragma unroll
            for (int mt = 0; mt < 4; mt++)
#pragma unroll
                for (int nt = 0; nt < 8; nt++)
                    mma16(acc[mt][nt], af[mt], bf[nt][0], bf[nt][1]);
        }
        __syncthreads();
    }

    // epilogue
#pragma unroll
    for (int mt = 0; mt < 4; mt++) {
#pragma unroll
        for (int nt = 0; nt < 8; nt++) {
            const int row = m0 + wm * 64 + mt * 16 + g;
            const int col = n0 + wn * 64 + nt * 8 + 2 * t;
            const float b0v = bias[col], b1v = bias[col + 1];
#pragma unroll
            for (int half_ = 0; half_ < 2; half_++) {
                const int r = row + half_ * 8;
                const float vx = acc[mt][nt][half_ * 2 + 0] + b0v;
                const float vy = acc[mt][nt][half_ * 2 + 1] + b1v;
                if (MODE == 0) {
                    float* C = (float*)Cv;
                    *reinterpret_cast<float2*>(C + (size_t)r * D_MODEL + col) =
                        make_float2(vx, vy);
                } else {
                    __half* C = (__half*)Cv;
                    const int bb = r >> 11, ss = r & (SEQ - 1);
                    const int hh = col >> 6, dd = col & (HEAD_DIM - 1);
                    *reinterpret_cast<unsigned*>(
                        C + (((size_t)(bb * NUM_HEADS + hh) * SEQ + ss) << 6)
                          + dd) = h2u(__floats2half2_rn(vx, vy));
                }
            }
        }
    }
}

// ---------------------------------------------------------------------------
// Flash attention (causal), fp16 operands / fp32 softmax+accum.
// Block = (b, h, 128-row q tile), 4 warps; warp covers 32 q rows (2 m-frags).
// smem (pair-packed words, stride 36): Qs[128], Ps[128], Ks[64], Vs[64].
// V stays K-major; PV B-fragments come from ldmatrix.x2.trans.
// ---------------------------------------------------------------------------
#define SKA 36
#define QS_OFF 0
#define PS_OFF (128 * SKA)
#define KS_OFF (256 * SKA)
#define VS_OFF (320 * SKA)
#define A_SMEM_BYTES ((384) * SKA * 4)    // 55296

__global__ __launch_bounds__(128)
void attn_kernel(const __half* __restrict__ gq, const __half* __restrict__ gk,
                 const __half* __restrict__ gv, __half* __restrict__ gout)
{
    extern __shared__ unsigned smu[];
    unsigned* Qs = smu + QS_OFF;
    unsigned* Ps = smu + PS_OFF;
    unsigned* Ks = smu + KS_OFF;
    unsigned* Vs = smu + VS_OFF;
    const unsigned vs_byte =
        (unsigned)__cvta_generic_to_shared(smu) + VS_OFF * 4;

    const int tid  = threadIdx.x;
    const int lane = tid & 31, w = tid >> 5;
    const int g = lane >> 2, t = lane & 3;
    const int qt = gridDim.x - 1 - blockIdx.x;   // long blocks first
    const int h = blockIdx.y, b = blockIdx.z;

    const size_t base = (size_t)(b * NUM_HEADS + h) * SEQ * HEAD_DIM;
    const __half* Q  = gq + base + (size_t)qt * 128 * HEAD_DIM;
    const __half* Kp = gk + base;
    const __half* Vp = gv + base;

    // Q tile -> smem (8 x uint4 per 64-half row)
    for (int i = tid; i < 128 * 8; i += 128) {
        const int r = i >> 3, c8 = i & 7;
        uint4 v4 = reinterpret_cast<const uint4*>(Q + r * HEAD_DIM)[c8];
        *reinterpret_cast<uint4*>(&Qs[r * SKA + c8 * 4]) = v4;
    }

    float oacc[2][8][4];
#pragma unroll
    for (int mt = 0; mt < 2; mt++)
#pragma unroll
        for (int i = 0; i < 8; i++)
#pragma unroll
            for (int e = 0; e < 4; e++) oacc[mt][i][e] = 0.f;

    float mr[4], ls[4];
#pragma unroll
    for (int i = 0; i < 4; i++) { mr[i] = -1e30f; ls[i] = 0.f; }

    const float sl = 0.125f * 1.4426950408889634f;   // SCALE * log2(e)
    const int njt = 2 * qt + 2;                      // 64-row k tiles

    for (int j = 0; j < njt; j++) {
        __syncthreads();
        const __half* Kj = Kp + (size_t)j * 64 * HEAD_DIM;
        const __half* Vj = Vp + (size_t)j * 64 * HEAD_DIM;
        for (int i = tid; i < 64 * 8; i += 128) {
            const int r = i >> 3, c8 = i & 7;
            uint4 kv = reinterpret_cast<const uint4*>(Kj + r * HEAD_DIM)[c8];
            *reinterpret_cast<uint4*>(&Ks[r * SKA + c8 * 4]) = kv;
            uint4 vv = reinterpret_cast<const uint4*>(Vj + r * HEAD_DIM)[c8];
            *reinterpret_cast<uint4*>(&Vs[r * SKA + c8 * 4]) = vv;
        }
        __syncthreads();

        // ---- S = Q K^T ----
        float sacc[2][8][4];
#pragma unroll
        for (int mt = 0; mt < 2; mt++)
#pragma unroll
            for (int i = 0; i < 8; i++)
#pragma unroll
                for (int e = 0; e < 4; e++) sacc[mt][i][e] = 0.f;

#pragma unroll
        for (int kk = 0; kk < 4; kk++) {       // k16 over HEAD_DIM
            const int c = kk * 8 + t;
            unsigned qa0[4], qa1[4];
            {
                const int r0 = w * 32 + g;
                qa0[0] = Qs[ r0       * SKA + c    ];
                qa0[1] = Qs[(r0 +  8) * SKA + c    ];
                qa0[2] = Qs[ r0       * SKA + c + 4];
                qa0[3] = Qs[(r0 +  8) * SKA + c + 4];
                qa1[0] = Qs[(r0 + 16) * SKA + c    ];
                qa1[1] = Qs[(r0 + 24) * SKA + c    ];
                qa1[2] = Qs[(r0 + 16) * SKA + c + 4];
                qa1[3] = Qs[(r0 + 24) * SKA + c + 4];
            }
#pragma unroll
            for (int nt = 0; nt < 8; nt++) {
                const int rn = nt * 8 + g;
                const unsigned b0 = Ks[rn * SKA + c];
                const unsigned b1 = Ks[rn * SKA + c + 4];
                mma16(sacc[0][nt], qa0, b0, b1);
                mma16(sacc[1][nt], qa1, b0, b1);
            }
        }

        // ---- scale + causal mask on diagonal region ----
        if (j >= 2 * qt) {
#pragma unroll
            for (int mt = 0; mt < 2; mt++)
#pragma unroll
                for (int nt = 0; nt < 8; nt++)
#pragma unroll
                    for (int e = 0; e < 4; e++) {
                        const int colg = j * 64 + nt * 8 + 2 * t + (e & 1);
                        const int rowg = qt * 128 + w * 32 + mt * 16 + g
                                       + ((e >> 1) << 3);
                        sacc[mt][nt][e] = (colg > rowg) ? -1e30f
                                                        : sacc[mt][nt][e] * sl;
                    }
        } else {
#pragma unroll
            for (int mt = 0; mt < 2; mt++)
#pragma unroll
                for (int nt = 0; nt < 8; nt++)
#pragma unroll
                    for (int e = 0; e < 4; e++) sacc[mt][nt][e] *= sl;
        }

        // ---- online softmax ----
#pragma unroll
        for (int mt = 0; mt < 2; mt++) {
            float mx0 = -1e30f, mx1 = -1e30f;
#pragma unroll
            for (int nt = 0; nt < 8; nt++) {
                mx0 = fmaxf(mx0, fmaxf(sacc[mt][nt][0], sacc[mt][nt][1]));
                mx1 = fmaxf(mx1, fmaxf(sacc[mt][nt][2], sacc[mt][nt][3]));
            }
            mx0 = fmaxf(mx0, __shfl_xor_sync(0xffffffffu, mx0, 1));
            mx0 = fmaxf(mx0, __shfl_xor_sync(0xffffffffu, mx0, 2));
            mx1 = fmaxf(mx1, __shfl_xor_sync(0xffffffffu, mx1, 1));
            mx1 = fmaxf(mx1, __shfl_xor_sync(0xffffffffu, mx1, 2));
            const float nm0 = fmaxf(mr[mt * 2 + 0], mx0);
            const float nm1 = fmaxf(mr[mt * 2 + 1], mx1);
            const float al0 = ex2f(mr[mt * 2 + 0] - nm0);
            const float al1 = ex2f(mr[mt * 2 + 1] - nm1);
            mr[mt * 2 + 0] = nm0; mr[mt * 2 + 1] = nm1;

            const int prow = w * 32 + mt * 16 + g;
            float ps0 = 0.f, ps1 = 0.f;
#pragma unroll
            for (int nt = 0; nt < 8; nt++) {
                const float p0 = ex2f(sacc[mt][nt][0] - nm0);
                const float p1 = ex2f(sacc[mt][nt][1] - nm0);
                const float p2 = ex2f(sacc[mt][nt][2] - nm1);
                const float p3 = ex2f(sacc[mt][nt][3] - nm1);
                ps0 += p0 + p1; ps1 += p2 + p3;
                Ps[ prow      * SKA + nt * 4 + t] = h2u(__floats2half2_rn(p0, p1));
                Ps[(prow + 8) * SKA + nt * 4 + t] = h2u(__floats2half2_rn(p2, p3));
            }
            ps0 += __shfl_xor_sync(0xffffffffu, ps0, 1);
            ps0 += __shfl_xor_sync(0xffffffffu, ps0, 2);
            ps1 += __shfl_xor_sync(0xffffffffu, ps1, 1);
            ps1 += __shfl_xor_sync(0xffffffffu, ps1, 2);
            ls[mt * 2 + 0] = ls[mt * 2 + 0] * al0 + ps0;
            ls[mt * 2 + 1] = ls[mt * 2 + 1] * al1 + ps1;
#pragma unroll
            for (int nt = 0; nt < 8; nt++) {
                oacc[mt][nt][0] *= al0; oacc[mt][nt][1] *= al0;
                oacc[mt][nt][2] *= al1; oacc[mt][nt][3] *= al1;
            }
        }
        __syncwarp();   // each warp reads only its own P rows

        // ---- O += P V  (A = P, B = V via ldmatrix.trans) ----
#pragma unroll
        for (int kk = 0; kk < 4; kk++) {       // k16 over 64 key positions
            const int c = kk * 8 + t;
            unsigned pa0[4], pa1[4];
            {
                const int r0 = w * 32 + g;
                pa0[0] = Ps[ r0       * SKA + c    ];
                pa0[1] = Ps[(r0 +  8) * SKA + c    ];
                pa0[2] = Ps[ r0       * SKA + c + 4];
                pa0[3] = Ps[(r0 +  8) * SKA + c + 4];
                pa1[0] = Ps[(r0 + 16) * SKA + c    ];
                pa1[1] = Ps[(r0 + 24) * SKA + c    ];
                pa1[2] = Ps[(r0 + 16) * SKA + c + 4];
                pa1[3] = Ps[(r0 + 24) * SKA + c + 4];
            }
            const unsigned vrow =
                vs_byte + (unsigned)(kk * 16 + (lane & 15)) * (SKA * 4);
#pragma unroll
            for (int nt = 0; nt < 8; nt++) {
                unsigned b0, b1;
                ldmx2t(b0, b1, vrow + nt * 16);
                mma16(oacc[0][nt], pa0, b0, b1);
                mma16(oacc[1][nt], pa1, b0, b1);
            }
        }
    }

    // ---- epilogue: normalize, fp16-round, scatter [B*S, D] ----
#pragma unroll
    for (int mt = 0; mt < 2; mt++) {
        const float il0 = 1.f / ls[mt * 2 + 0];
        const float il1 = 1.f / ls[mt * 2 + 1];
        const int qrow = qt * 128 + w * 32 + mt * 16 + g;
        __half* O0 = gout + (size_t)(b * SEQ + qrow) * D_MODEL + h * HEAD_DIM;
        __half* O1 = O0 + 8 * D_MODEL;
#pragma unroll
        for (int nt = 0; nt < 8; nt++) {
            const int col = nt * 8 + 2 * t;
            *reinterpret_cast<unsigned*>(O0 + col) =
                h2u(__floats2half2_rn(oacc[mt][nt][0] * il0,
                                      oacc[mt][nt][1] * il0));
            *reinterpret_cast<unsigned*>(O1 + col) =
                h2u(__floats2half2_rn(oacc[mt][nt][2] * il1,
                                      oacc[mt][nt][3] * il1));
        }
    }
}

// ---------------------------------------------------------------------------
// Launch
// ---------------------------------------------------------------------------
extern "C" void kernel_launch(void* const* d_in, const int* in_sizes, int n_in,
                              void* d_out, int out_size)
{
    const float* x  = (const float*)d_in[0];
    const float* Wq = (const float*)d_in[1];
    const float* bq = (const float*)d_in[2];
    const float* Wk = (const float*)d_in[3];
    const float* bk = (const float*)d_in[4];
    const float* Wv = (const float*)d_in[5];
    const float* bv = (const float*)d_in[6];
    const float* Wo = (const float*)d_in[7];
    const float* bo = (const float*)d_in[8];
    float* out = (float*)d_out;

    __half *q, *k, *v, *ao, *xh, *wq, *wk, *wv, *wo;
    cudaGetSymbolAddress((void**)&q,  g_q);
    cudaGetSymbolAddress((void**)&k,  g_k);
    cudaGetSymbolAddress((void**)&v,  g_v);
    cudaGetSymbolAddress((void**)&ao, g_ao);
    cudaGetSymbolAddress((void**)&xh, g_xh);
    cudaGetSymbolAddress((void**)&wq, g_wq);
    cudaGetSymbolAddress((void**)&wk, g_wk);
    cudaGetSymbolAddress((void**)&wv, g_wv);
    cudaGetSymbolAddress((void**)&wo, g_wo);

    to_half_k<<<1024, 256>>>((const float4*)x,  (uint2*)xh, MTOT * D_MODEL / 4);
    to_half_k<<<512,  256>>>((const float4*)Wq, (uint2*)wq, D_MODEL * D_MODEL / 4);
    to_half_k<<<512,  256>>>((const float4*)Wk, (uint2*)wk, D_MODEL * D_MODEL / 4);
    to_half_k<<<512,  256>>>((const float4*)Wv, (uint2*)wv, D_MODEL * D_MODEL / 4);
    to_half_k<<<512,  256>>>((const float4*)Wo, (uint2*)wo, D_MODEL * D_MODEL / 4);

    const int gsmem = 4 * GSTAGE * 4;   // 73728 B
    cudaFuncSetAttribute(gemm_h<0>,
        cudaFuncAttributeMaxDynamicSharedMemorySize, gsmem);
    cudaFuncSetAttribute(gemm_h<1>,
        cudaFuncAttributeMaxDynamicSharedMemorySize, gsmem);
    cudaFuncSetAttribute(attn_kernel,
        cudaFuncAttributeMaxDynamicSharedMemorySize, A_SMEM_BYTES);

    const dim3 ggrid(D_MODEL / 128, MTOT / 128);   // (8, 32)
    gemm_h<1><<<ggrid, 128, gsmem>>>(xh, wq, bq, q);
    gemm_h<1><<<ggrid, 128, gsmem>>>(xh, wk, bk, k);
    gemm_h<1><<<ggrid, 128, gsmem>>>(xh, wv, bv, v);

    const dim3 agrid(SEQ / 128, NUM_HEADS, BATCH);  // (16, 16, 2)
    attn_kernel<<<agrid, 128, A_SMEM_BYTES>>>(q, k, v, ao);

    gemm_h<0><<<ggrid, 128, gsmem>>>(ao, wo, bo, out);
}

// round 5
// speedup vs baseline: 2.3612x; 1.1903x over previous
#include <cuda_runtime.h>
#include <cuda_fp16.h>
#include <cstdint>

#define D_MODEL   1024
#define NUM_HEADS 16
#define HEAD_DIM  64
#define SEQ       2048
#define BATCH     2
#define MTOT      (BATCH * SEQ)

// ---------------------------------------------------------------------------
// Scratch (device globals; allocation forbidden)
// ---------------------------------------------------------------------------
__device__ __half g_q [BATCH * NUM_HEADS * SEQ * HEAD_DIM];
__device__ __half g_k [BATCH * NUM_HEADS * SEQ * HEAD_DIM];
__device__ __half g_v [BATCH * NUM_HEADS * SEQ * HEAD_DIM];
__device__ __half g_ao[MTOT * D_MODEL];
__device__ __half g_xh[MTOT * D_MODEL];
__device__ __half g_wq[D_MODEL * D_MODEL];
__device__ __half g_wk[D_MODEL * D_MODEL];
__device__ __half g_wv[D_MODEL * D_MODEL];
__device__ __half g_wo[D_MODEL * D_MODEL];

// ---------------------------------------------------------------------------
// Helpers
// ---------------------------------------------------------------------------
__device__ __forceinline__ float ex2f(float x) {
    float y;
    asm("ex2.approx.f32 %0, %1;" : "=f"(y) : "f"(x));
    return y;
}

__device__ __forceinline__ void mma16(float c[4], const unsigned a[4],
                                      unsigned b0, unsigned b1) {
    asm volatile(
        "mma.sync.aligned.m16n8k16.row.col.f32.f16.f16.f32 "
        "{%0,%1,%2,%3},{%4,%5,%6,%7},{%8,%9},{%0,%1,%2,%3};"
        : "+f"(c[0]), "+f"(c[1]), "+f"(c[2]), "+f"(c[3])
        : "r"(a[0]), "r"(a[1]), "r"(a[2]), "r"(a[3]), "r"(b0), "r"(b1));
}

__device__ __forceinline__ void cp16(void* sdst, const void* gsrc) {
    unsigned s = (unsigned)__cvta_generic_to_shared(sdst);
    asm volatile("cp.async.cg.shared.global [%0], [%1], 16;\n"
                 :: "r"(s), "l"(gsrc));
}

__device__ __forceinline__ void ldsm4(unsigned& r0, unsigned& r1,
                                      unsigned& r2, unsigned& r3,
                                      unsigned addr) {
    asm volatile(
        "ldmatrix.sync.aligned.m8n8.x4.shared.b16 {%0,%1,%2,%3}, [%4];"
        : "=r"(r0), "=r"(r1), "=r"(r2), "=r"(r3) : "r"(addr));
}

__device__ __forceinline__ void ldsm4t(unsigned& r0, unsigned& r1,
                                       unsigned& r2, unsigned& r3,
                                       unsigned addr) {
    asm volatile(
        "ldmatrix.sync.aligned.m8n8.x4.trans.shared.b16 {%0,%1,%2,%3}, [%4];"
        : "=r"(r0), "=r"(r1), "=r"(r2), "=r"(r3) : "r"(addr));
}

__device__ __forceinline__ unsigned h2u(__half2 h) {
    return *reinterpret_cast<unsigned*>(&h);
}

// ---------------------------------------------------------------------------
// Fused fp32 -> fp16 convert (x + 4 weights in one launch)
// ---------------------------------------------------------------------------
#define NX4 (MTOT * D_MODEL / 4)        // 1048576
#define NW4 (D_MODEL * D_MODEL / 4)     // 262144

__global__ void to_half_all(
    const float4* __restrict__ x,  const float4* __restrict__ wq,
    const float4* __restrict__ wk, const float4* __restrict__ wv,
    const float4* __restrict__ wo,
    uint2* __restrict__ xh, uint2* __restrict__ oq, uint2* __restrict__ ok,
    uint2* __restrict__ ov, uint2* __restrict__ oo)
{
    const int total = NX4 + 4 * NW4;
    for (int i = blockIdx.x * blockDim.x + threadIdx.x; i < total;
         i += gridDim.x * blockDim.x) {
        const float4* src;
        uint2* dst;
        int off;
        if (i < NX4) { src = x; dst = xh; off = i; }
        else {
            const int j = i - NX4, w = j >> 18;
            off = j & (NW4 - 1);
            src = (w == 0) ? wq : (w == 1) ? wk : (w == 2) ? wv : wo;
            dst = (w == 0) ? oq : (w == 1) ? ok : (w == 2) ? ov : oo;
        }
        float4 v = src[off];
        uint2 o;
        o.x = h2u(__floats2half2_rn(v.x, v.y));
        o.y = h2u(__floats2half2_rn(v.z, v.w));
        dst[off] = o;
    }
}

// ---------------------------------------------------------------------------
// NT GEMM (fp16 in / fp32 accum): C[m,n] = sum_k A[m,k]*W[n,k] + bias[n]
// CTA tile 128(m) x 256(n), 256 threads = 8 warps (2x4), warp tile 64x64.
// K-chunk 64, 2-stage cp.async, ldmatrix fragment loads.
// MODE 0: fp32 row-major out.  MODE 1: fp16 scatter to [B,H,S,hd].
// ---------------------------------------------------------------------------
#define GSA    36                          // words per row (64 halves + pad)
#define GROWB  144                         // bytes per row
#define STAGEW ((128 + 256) * GSA)         // 13824 words per stage
#define GSMEM_BYTES (2 * STAGEW * 4)       // 110592

template <int MODE>
__global__ __launch_bounds__(256)
void gemm_h(const __half* __restrict__ A, const __half* __restrict__ W,
            const float* __restrict__ bias, void* __restrict__ Cv)
{
    extern __shared__ unsigned sm[];
    const unsigned smem_byte = (unsigned)__cvta_generic_to_shared(sm);
    const int tid = threadIdx.x, lane = tid & 31, wid = tid >> 5;
    const int wm = wid & 1, wn = wid >> 1;            // 2 x 4 warps
    const int m0 = blockIdx.y * 128, n0 = blockIdx.x * 256;

    float acc[4][8][4];
#pragma unroll
    for (int i = 0; i < 4; i++)
#pragma unroll
        for (int j = 0; j < 8; j++)
#pragma unroll
            for (int e = 0; e < 4; e++) acc[i][j][e] = 0.f;

    auto issue = [&](int s, int k0) {
        unsigned* dA = sm + s * STAGEW;
        unsigned* dB = dA + 128 * GSA;
        const __half* Ap = A + (size_t)m0 * D_MODEL + k0;
        const __half* Bp = W + (size_t)n0 * D_MODEL + k0;
#pragma unroll
        for (int i = 0; i < 4; i++) {           // A: 128 rows x 8 chunks
            const int lin = tid + i * 256;
            const int r = lin >> 3, c8 = lin & 7;
            cp16(dA + r * GSA + c8 * 4, Ap + (size_t)r * D_MODEL + c8 * 8);
        }
#pragma unroll
        for (int i = 0; i < 8; i++) {           // B: 256 rows x 8 chunks
            const int lin = tid + i * 256;
            const int r = lin >> 3, c8 = lin & 7;
            cp16(dB + r * GSA + c8 * 4, Bp + (size_t)r * D_MODEL + c8 * 8);
        }
        asm volatile("cp.async.commit_group;\n" ::: "memory");
    };

    // lane-dependent ldmatrix address parts
    const unsigned a_lane =
        (unsigned)((wm * 64 + (lane & 15)) * GROWB + (lane >> 4) * 16);
    const unsigned b_lane =
        (unsigned)((wn * 64 + ((lane >> 3) & 1) * 8 + (lane & 7)) * GROWB
                   + (lane >> 4) * 16);

    issue(0, 0);
    const int T = D_MODEL / 64;   // 16 chunks
    for (int tt = 0; tt < T; tt++) {
        const int s = tt & 1;
        if (tt + 1 < T) {
            issue(s ^ 1, (tt + 1) * 64);
            asm volatile("cp.async.wait_group 1;\n" ::: "memory");
        } else {
            asm volatile("cp.async.wait_group 0;\n" ::: "memory");
        }
        __syncthreads();

        const unsigned aBase = smem_byte + s * STAGEW * 4 + a_lane;
        const unsigned bBase = smem_byte + s * STAGEW * 4 + 128 * GROWB + b_lane;
#pragma unroll
        for (int kk = 0; kk < 4; kk++) {
            unsigned af[4][4], bf[8][2];
#pragma unroll
            for (int mt = 0; mt < 4; mt++)
                ldsm4(af[mt][0], af[mt][1], af[mt][2], af[mt][3],
                      aBase + mt * 16 * GROWB + kk * 32);
#pragma unroll
            for (int p = 0; p < 4; p++) {
                unsigned r0, r1, r2, r3;
                ldsm4(r0, r1, r2, r3, bBase + p * 16 * GROWB + kk * 32);
                bf[2 * p][0] = r0; bf[2 * p + 1][0] = r1;
                bf[2 * p][1] = r2; bf[2 * p + 1][1] = r3;
            }
#pragma unroll
            for (int mt = 0; mt < 4; mt++)
#pragma unroll
                for (int nt = 0; nt < 8; nt++)
                    mma16(acc[mt][nt], af[mt], bf[nt][0], bf[nt][1]);
        }
        __syncthreads();
    }

    // epilogue
    const int g = lane >> 2, t = lane & 3;
#pragma unroll
    for (int mt = 0; mt < 4; mt++) {
#pragma unroll
        for (int nt = 0; nt < 8; nt++) {
            const int row = m0 + wm * 64 + mt * 16 + g;
            const int col = n0 + wn * 64 + nt * 8 + 2 * t;
            const float b0v = bias[col], b1v = bias[col + 1];
#pragma unroll
            for (int hf = 0; hf < 2; hf++) {
                const int r = row + hf * 8;
                const float vx = acc[mt][nt][hf * 2 + 0] + b0v;
                const float vy = acc[mt][nt][hf * 2 + 1] + b1v;
                if (MODE == 0) {
                    float* C = (float*)Cv;
                    *reinterpret_cast<float2*>(C + (size_t)r * D_MODEL + col) =
                        make_float2(vx, vy);
                } else {
                    __half* C = (__half*)Cv;
                    const int bb = r >> 11, ss = r & (SEQ - 1);
                    const int hh = col >> 6, dd = col & (HEAD_DIM - 1);
                    *reinterpret_cast<unsigned*>(
                        C + (((size_t)(bb * NUM_HEADS + hh) * SEQ + ss) << 6)
                          + dd) = h2u(__floats2half2_rn(vx, vy));
                }
            }
        }
    }
}

// ---------------------------------------------------------------------------
// Flash attention (causal).  Block = (b, h, 128-row q tile), 4 warps.
// Warp covers 32 q rows (2 m-frags).  K/V 64-row tiles, cp.async 2-stage.
// Q fragments live in registers (ldmatrix once).  All fragment loads via
// ldmatrix.  smem: Ps[128 rows] (Q staging then P), Ks[2][64], Vs[2][64].
// ---------------------------------------------------------------------------
#define KS_OFF (128 * GSA)                  // words
#define VS_OFF (KS_OFF + 2 * 64 * GSA)
#define KVSTGW (64 * GSA)                   // 2304 words per K or V stage
#define A_SMEM_BYTES ((VS_OFF + 2 * 64 * GSA) * 4)   // 55296

__global__ __launch_bounds__(128)
void attn_kernel(const __half* __restrict__ gq, const __half* __restrict__ gk,
                 const __half* __restrict__ gv, __half* __restrict__ gout)
{
    extern __shared__ unsigned smu[];
    unsigned* Ps = smu;
    const unsigned smem_byte = (unsigned)__cvta_generic_to_shared(smu);

    const int tid  = threadIdx.x;
    const int lane = tid & 31, w = tid >> 5;
    const int g = lane >> 2, t = lane & 3;
    const int qt = gridDim.x - 1 - blockIdx.x;    // long blocks first
    const int h = blockIdx.y, b = blockIdx.z;

    const size_t base = (size_t)(b * NUM_HEADS + h) * SEQ * HEAD_DIM;
    const __half* Q  = gq + base + (size_t)qt * 128 * HEAD_DIM;
    const __half* Kp = gk + base;
    const __half* Vp = gv + base;

    // ---- stage Q through Ps, then ldmatrix into registers ----
    for (int i = tid; i < 128 * 8; i += 128) {
        const int r = i >> 3, c8 = i & 7;
        uint4 v4 = reinterpret_cast<const uint4*>(Q + r * HEAD_DIM)[c8];
        *reinterpret_cast<uint4*>(&Ps[r * GSA + c8 * 4]) = v4;
    }
    __syncthreads();

    const unsigned amat_lane =
        (unsigned)((w * 32 + (lane & 15)) * GROWB + (lane >> 4) * 16);
    unsigned qf[4][2][4];   // [kk][mt][frag]
#pragma unroll
    for (int kk = 0; kk < 4; kk++)
#pragma unroll
        for (int mt = 0; mt < 2; mt++)
            ldsm4(qf[kk][mt][0], qf[kk][mt][1], qf[kk][mt][2], qf[kk][mt][3],
                  smem_byte + amat_lane + mt * 16 * GROWB + kk * 32);
    __syncthreads();   // Ps free for P

    float oacc[2][8][4];
#pragma unroll
    for (int mt = 0; mt < 2; mt++)
#pragma unroll
        for (int i = 0; i < 8; i++)
#pragma unroll
            for (int e = 0; e < 4; e++) oacc[mt][i][e] = 0.f;

    float mr[4], ls[4];
#pragma unroll
    for (int i = 0; i < 4; i++) { mr[i] = -1e30f; ls[i] = 0.f; }

    const float sl = 0.125f * 1.4426950408889634f;   // SCALE * log2(e)
    const int njt = 2 * qt + 2;

    auto issueKV = [&](int s, int j) {
        const __half* Kj = Kp + (size_t)j * 64 * HEAD_DIM;
        const __half* Vj = Vp + (size_t)j * 64 * HEAD_DIM;
        unsigned* dK = smu + KS_OFF + s * KVSTGW;
        unsigned* dV = smu + VS_OFF + s * KVSTGW;
#pragma unroll
        for (int i = 0; i < 4; i++) {
            const int lin = tid + i * 128;
            const int r = lin >> 3, c8 = lin & 7;
            cp16(dK + r * GSA + c8 * 4, Kj + r * HEAD_DIM + c8 * 8);
        }
#pragma unroll
        for (int i = 0; i < 4; i++) {
            const int lin = tid + i * 128;
            const int r = lin >> 3, c8 = lin & 7;
            cp16(dV + r * GSA + c8 * 4, Vj + r * HEAD_DIM + c8 * 8);
        }
        asm volatile("cp.async.commit_group;\n" ::: "memory");
    };

    const unsigned bmat_lane =
        (unsigned)((((lane >> 3) & 1) * 8 + (lane & 7)) * GROWB
                   + (lane >> 4) * 16);
    const unsigned vmat_lane =
        (unsigned)((((lane >> 3) & 1) * 8 + (lane & 7)) * GROWB
                   + (lane >> 4) * 16);

    issueKV(0, 0);
    for (int j = 0; j < njt; j++) {
        const int s = j & 1;
        if (j + 1 < njt) {
            issueKV(s ^ 1, j + 1);
            asm volatile("cp.async.wait_group 1;\n" ::: "memory");
        } else {
            asm volatile("cp.async.wait_group 0;\n" ::: "memory");
        }
        __syncthreads();

        const unsigned ksb = smem_byte + (KS_OFF + s * KVSTGW) * 4;
        const unsigned vsb = smem_byte + (VS_OFF + s * KVSTGW) * 4;

        // ---- S = Q K^T ----
        float sacc[2][8][4];
#pragma unroll
        for (int mt = 0; mt < 2; mt++)
#pragma unroll
            for (int i = 0; i < 8; i++)
#pragma unroll
                for (int e = 0; e < 4; e++) sacc[mt][i][e] = 0.f;

#pragma unroll
        for (int kk = 0; kk < 4; kk++) {
            unsigned bf[8][2];
#pragma unroll
            for (int p = 0; p < 4; p++) {
                unsigned r0, r1, r2, r3;
                ldsm4(r0, r1, r2, r3,
                      ksb + bmat_lane + p * 16 * GROWB + kk * 32);
                bf[2 * p][0] = r0; bf[2 * p + 1][0] = r1;
                bf[2 * p][1] = r2; bf[2 * p + 1][1] = r3;
            }
#pragma unroll
            for (int nt = 0; nt < 8; nt++) {
                mma16(sacc[0][nt], qf[kk][0], bf[nt][0], bf[nt][1]);
                mma16(sacc[1][nt], qf[kk][1], bf[nt][0], bf[nt][1]);
            }
        }

        // ---- scale + causal mask ----
        if (j >= 2 * qt) {
#pragma unroll
            for (int mt = 0; mt < 2; mt++)
#pragma unroll
                for (int nt = 0; nt < 8; nt++)
#pragma unroll
                    for (int e = 0; e < 4; e++) {
                        const int colg = j * 64 + nt * 8 + 2 * t + (e & 1);
                        const int rowg = qt * 128 + w * 32 + mt * 16 + g
                                       + ((e >> 1) << 3);
                        sacc[mt][nt][e] = (colg > rowg) ? -1e30f
                                                        : sacc[mt][nt][e] * sl;
                    }
        } else {
#pragma unroll
            for (int mt = 0; mt < 2; mt++)
#pragma unroll
                for (int nt = 0; nt < 8; nt++)
#pragma unroll
                    for (int e = 0; e < 4; e++) sacc[mt][nt][e] *= sl;
        }

        // ---- online softmax ----
#pragma unroll
        for (int mt = 0; mt < 2; mt++) {
            float mx0 = -1e30f, mx1 = -1e30f;
#pragma unroll
            for (int nt = 0; nt < 8; nt++) {
                mx0 = fmaxf(mx0, fmaxf(sacc[mt][nt][0], sacc[mt][nt][1]));
                mx1 = fmaxf(mx1, fmaxf(sacc[mt][nt][2], sacc[mt][nt][3]));
            }
            mx0 = fmaxf(mx0, __shfl_xor_sync(0xffffffffu, mx0, 1));
            mx0 = fmaxf(mx0, __shfl_xor_sync(0xffffffffu, mx0, 2));
            mx1 = fmaxf(mx1, __shfl_xor_sync(0xffffffffu, mx1, 1));
            mx1 = fmaxf(mx1, __shfl_xor_sync(0xffffffffu, mx1, 2));
            const float nm0 = fmaxf(mr[mt * 2 + 0], mx0);
            const float nm1 = fmaxf(mr[mt * 2 + 1], mx1);
            const float al0 = ex2f(mr[mt * 2 + 0] - nm0);
            const float al1 = ex2f(mr[mt * 2 + 1] - nm1);
            mr[mt * 2 + 0] = nm0; mr[mt * 2 + 1] = nm1;

            const int prow = w * 32 + mt * 16 + g;
            float ps0 = 0.f, ps1 = 0.f;
#pragma unroll
            for (int nt = 0; nt < 8; nt++) {
                const float p0 = ex2f(sacc[mt][nt][0] - nm0);
                const float p1 = ex2f(sacc[mt][nt][1] - nm0);
                const float p2 = ex2f(sacc[mt][nt][2] - nm1);
                const float p3 = ex2f(sacc[mt][nt][3] - nm1);
                ps0 += p0 + p1; ps1 += p2 + p3;
                Ps[ prow      * GSA + nt * 4 + t] = h2u(__floats2half2_rn(p0, p1));
                Ps[(prow + 8) * GSA + nt * 4 + t] = h2u(__floats2half2_rn(p2, p3));
            }
            ps0 += __shfl_xor_sync(0xffffffffu, ps0, 1);
            ps0 += __shfl_xor_sync(0xffffffffu, ps0, 2);
            ps1 += __shfl_xor_sync(0xffffffffu, ps1, 1);
            ps1 += __shfl_xor_sync(0xffffffffu, ps1, 2);
            ls[mt * 2 + 0] = ls[mt * 2 + 0] * al0 + ps0;
            ls[mt * 2 + 1] = ls[mt * 2 + 1] * al1 + ps1;
#pragma unroll
            for (int nt = 0; nt < 8; nt++) {
                oacc[mt][nt][0] *= al0; oacc[mt][nt][1] *= al0;
                oacc[mt][nt][2] *= al1; oacc[mt][nt][3] *= al1;
            }
        }
        __syncwarp();   // each warp reads only its own P rows

        // ---- O += P V ----
#pragma unroll
        for (int kk = 0; kk < 4; kk++) {       // k16 over 64 keys
            unsigned pa[2][4];
#pragma unroll
            for (int mt = 0; mt < 2; mt++)
                ldsm4(pa[mt][0], pa[mt][1], pa[mt][2], pa[mt][3],
                      smem_byte + amat_lane + mt * 16 * GROWB + kk * 32);
#pragma unroll
            for (int p = 0; p < 4; p++) {      // nt = 2p, 2p+1
                unsigned r0, r1, r2, r3;
                ldsm4t(r0, r1, r2, r3,
                       vsb + (unsigned)(kk * 16) * GROWB + vmat_lane
                           + (unsigned)(2 * p) * 16);
                mma16(oacc[0][2 * p    ], pa[0], r0, r1);
                mma16(oacc[1][2 * p    ], pa[1], r0, r1);
                mma16(oacc[0][2 * p + 1], pa[0], r2, r3);
                mma16(oacc[1][2 * p + 1], pa[1], r2, r3);
            }
        }
        __syncthreads();   // done with Ks/Vs stage s before it is refilled
    }

    // ---- epilogue ----
#pragma unroll
    for (int mt = 0; mt < 2; mt++) {
        const float il0 = 1.f / ls[mt * 2 + 0];
        const float il1 = 1.f / ls[mt * 2 + 1];
        const int qrow = qt * 128 + w * 32 + mt * 16 + g;
        __half* O0 = gout + (size_t)(b * SEQ + qrow) * D_MODEL + h * HEAD_DIM;
        __half* O1 = O0 + 8 * D_MODEL;
#pragma unroll
        for (int nt = 0; nt < 8; nt++) {
            const int col = nt * 8 + 2 * t;
            *reinterpret_cast<unsigned*>(O0 + col) =
                h2u(__floats2half2_rn(oacc[mt][nt][0] * il0,
                                      oacc[mt][nt][1] * il0));
            *reinterpret_cast<unsigned*>(O1 + col) =
                h2u(__floats2half2_rn(oacc[mt][nt][2] * il1,
                                      oacc[mt][nt][3] * il1));
        }
    }
}

// ---------------------------------------------------------------------------
// Launch
// ---------------------------------------------------------------------------
extern "C" void kernel_launch(void* const* d_in, const int* in_sizes, int n_in,
                              void* d_out, int out_size)
{
    const float* x  = (const float*)d_in[0];
    const float* Wq = (const float*)d_in[1];
    const float* bq = (const float*)d_in[2];
    const float* Wk = (const float*)d_in[3];
    const float* bk = (const float*)d_in[4];
    const float* Wv = (const float*)d_in[5];
    const float* bv = (const float*)d_in[6];
    const float* Wo = (const float*)d_in[7];
    const float* bo = (const float*)d_in[8];
    float* out = (float*)d_out;

    __half *q, *k, *v, *ao, *xh, *wq, *wk, *wv, *wo;
    cudaGetSymbolAddress((void**)&q,  g_q);
    cudaGetSymbolAddress((void**)&k,  g_k);
    cudaGetSymbolAddress((void**)&v,  g_v);
    cudaGetSymbolAddress((void**)&ao, g_ao);
    cudaGetSymbolAddress((void**)&xh, g_xh);
    cudaGetSymbolAddress((void**)&wq, g_wq);
    cudaGetSymbolAddress((void**)&wk, g_wk);
    cudaGetSymbolAddress((void**)&wv, g_wv);
    cudaGetSymbolAddress((void**)&wo, g_wo);

    to_half_all<<<2048, 256>>>((const float4*)x,  (const float4*)Wq,
                               (const float4*)Wk, (const float4*)Wv,
                               (const float4*)Wo,
                               (uint2*)xh, (uint2*)wq, (uint2*)wk,
                               (uint2*)wv, (uint2*)wo);

    cudaFuncSetAttribute(gemm_h<0>,
        cudaFuncAttributeMaxDynamicSharedMemorySize, GSMEM_BYTES);
    cudaFuncSetAttribute(gemm_h<1>,
        cudaFuncAttributeMaxDynamicSharedMemorySize, GSMEM_BYTES);
    cudaFuncSetAttribute(attn_kernel,
        cudaFuncAttributeMaxDynamicSharedMemorySize, A_SMEM_BYTES);

    const dim3 ggrid(D_MODEL / 256, MTOT / 128);   // (4, 32) = 128 CTAs
    gemm_h<1><<<ggrid, 256, GSMEM_BYTES>>>(xh, wq, bq, q);
    gemm_h<1><<<ggrid, 256, GSMEM_BYTES>>>(xh, wk, bk, k);
    gemm_h<1><<<ggrid, 256, GSMEM_BYTES>>>(xh, wv, bv, v);

    const dim3 agrid(SEQ / 128, NUM_HEADS, BATCH);  // (16, 16, 2)
    attn_kernel<<<agrid, 128, A_SMEM_BYTES>>>(q, k, v, ao);

    gemm_h<0><<<ggrid, 256, GSMEM_BYTES>>>(ao, wo, bo, out);
}